// round 6
// baseline (speedup 1.0000x reference)
#include <cuda_runtime.h>
#include <cstdint>

#define DEV_INLINE __device__ __forceinline__

constexpr int Bn = 1024, Tn = 128, In = 128, Hn = 1024, G4 = 4096, On = 64;
constexpr int K_TOT = In + Hn;          // 1152
constexpr int KC = 32;                  // K floats per chunk
constexpr int NCHUNK = K_TOT / KC;      // 36
constexpr int MT = 128, NT = 256;
constexpr int SPAD = 36;                // padded row stride (floats): bank = 4g+t, conflict-free

__device__ float g_h[Bn * Hn];
__device__ float g_c[Bn * Hn];
__device__ float g_w[G4 * K_TOT];       // [w_ih | w_hh], tf32-rounded, row n has K_TOT cols
__device__ float g_x[Bn * Tn * In];     // tf32-rounded x

// SMEM layout (bytes): bias 256 floats, then A/B double-buffered padded tiles
constexpr int SM_BIAS = 0;
constexpr int SM_A0 = 1024;
constexpr int A_BYTES = MT * SPAD * 4;        // 18432
constexpr int SM_A1 = SM_A0 + A_BYTES;
constexpr int SM_B0 = SM_A1 + A_BYTES;
constexpr int B_BYTES = NT * SPAD * 4;        // 36864
constexpr int SM_B1 = SM_B0 + B_BYTES;
constexpr int SMEM_BYTES = SM_B1 + B_BYTES;   // 111616

#define CPA16(dst, src) asm volatile("cp.async.cg.shared.global [%0], [%1], 16;" :: "r"(dst), "l"(src))
#define CP_COMMIT()     asm volatile("cp.async.commit_group;" ::: "memory")
#define CP_WAIT_1()     asm volatile("cp.async.wait_group 1;" ::: "memory")
#define CP_WAIT_0()     asm volatile("cp.async.wait_group 0;" ::: "memory")

DEV_INLINE uint32_t smem_u32(const void* p) {
    uint32_t a;
    asm("{ .reg .u64 t; cvta.to.shared.u64 t, %1; cvt.u32.u64 %0, t; }" : "=r"(a) : "l"(p));
    return a;
}

DEV_INLINE void mma8(float* c, const uint32_t* a, const uint32_t* b) {
    asm volatile(
        "mma.sync.aligned.m16n8k8.row.col.f32.tf32.tf32.f32 "
        "{%0,%1,%2,%3}, {%4,%5,%6,%7}, {%8,%9}, {%0,%1,%2,%3};"
        : "+f"(c[0]), "+f"(c[1]), "+f"(c[2]), "+f"(c[3])
        : "r"(a[0]), "r"(a[1]), "r"(a[2]), "r"(a[3]), "r"(b[0]), "r"(b[1]));
}

DEV_INLINE float sigf(float x) {
    float e, r;
    asm("ex2.approx.f32 %0, %1;" : "=f"(e) : "f"(-1.4426950408889634f * x));
    asm("rcp.approx.f32 %0, %1;" : "=f"(r) : "f"(1.0f + e));
    return r;
}
DEV_INLINE float tanhf_(float x) { return 2.0f * sigf(2.0f * x) - 1.0f; }
DEV_INLINE float tf32r(float x) {
    uint32_t u;
    asm("cvt.rna.tf32.f32 %0, %1;" : "=r"(u) : "f"(x));
    return __uint_as_float(u);
}

// ---------------- prep ----------------
__global__ void init_hc_kernel() {
    int i = blockIdx.x * blockDim.x + threadIdx.x;
    if (i < Bn * Hn) { g_h[i] = 0.0f; g_c[i] = 0.0f; }
}
__global__ void prep_w_kernel(const float* __restrict__ w_ih, const float* __restrict__ w_hh) {
    int i = blockIdx.x * blockDim.x + threadIdx.x;
    if (i >= G4 * K_TOT) return;
    int n = i / K_TOT, k = i - n * K_TOT;
    g_w[i] = tf32r(k < In ? w_ih[n * In + k] : w_hh[n * Hn + (k - In)]);
}
__global__ void prep_x_kernel(const float* __restrict__ x) {
    int i = blockIdx.x * blockDim.x + threadIdx.x;
    if (i < Bn * Tn * In) g_x[i] = tf32r(x[i]);
}

// ---------------- chunk loader (padded, unswizzled) ----------------
DEV_INLINE void load_chunk(int kc, int m0, int nbase, uint32_t sA, uint32_t sB, int t, int tid) {
    int k0 = kc * KC;
    const float* abase;
    int apitch;
    if (k0 < In) { abase = g_x + (size_t)m0 * (Tn * In) + t * In + k0; apitch = Tn * In; }
    else         { abase = g_h + (size_t)m0 * Hn + (k0 - In);          apitch = Hn; }
#pragma unroll
    for (int j = 0; j < 4; j++) {               // A: 128 rows x 8 segs of 16B
        int op = j * 256 + tid, row = op >> 3, seg = op & 7;
        CPA16(sA + row * (SPAD * 4) + seg * 16, abase + (size_t)row * apitch + seg * 4);
    }
    const float* wbase = g_w + k0;
#pragma unroll
    for (int j = 0; j < 8; j++) {               // B: 256 gathered gate rows x 8 segs
        int op = j * 256 + tid, rb = op >> 3, seg = op & 7;
        int n = ((rb >> 6) << 10) + nbase + (rb & 63);
        CPA16(sB + rb * (SPAD * 4) + seg * 16, wbase + (size_t)n * K_TOT + seg * 4);
    }
}

// ---------------- LSTM step ----------------
__global__ void __launch_bounds__(256, 1)
lstm_step_kernel(int t, const float* __restrict__ b_ih, const float* __restrict__ b_hh) {
    extern __shared__ char smem[];
    uint32_t sb = smem_u32(smem);
    int tid = threadIdx.x, wid = tid >> 5, lid = tid & 31;
    int wm = wid >> 2, wn = wid & 3;            // warp grid 2(m) x 4(n)
    int g = lid >> 2, tg = lid & 3;             // mma group / thread-in-group
    int m0 = blockIdx.x * MT, nbase = blockIdx.y * 64;

    {   // bias_sum for this CTA's 256 gathered gate columns
        int n = ((tid >> 6) << 10) + nbase + (tid & 63);
        ((float*)(smem + SM_BIAS))[tid] = b_ih[n] + b_hh[n];
    }

    float acc[4][8][4];
#pragma unroll
    for (int mt = 0; mt < 4; mt++)
#pragma unroll
        for (int j = 0; j < 8; j++)
#pragma unroll
            for (int q = 0; q < 4; q++) acc[mt][j][q] = 0.0f;

    load_chunk(0, m0, nbase, sb + SM_A0, sb + SM_B0, t, tid);
    CP_COMMIT();

    for (int kc = 0; kc < NCHUNK; kc++) {
        int cur = kc & 1;
        if (kc + 1 < NCHUNK) {
            load_chunk(kc + 1, m0, nbase, cur ? (sb + SM_A0) : (sb + SM_A1),
                       cur ? (sb + SM_B0) : (sb + SM_B1), t, tid);
            CP_COMMIT();
            CP_WAIT_1();                        // chunk kc has landed
        } else {
            CP_WAIT_0();
        }
        __syncthreads();                        // chunk kc visible to all threads

        const float* As = (const float*)(smem + (cur ? SM_A1 : SM_A0));
        const float* Bs = (const float*)(smem + (cur ? SM_B1 : SM_B0));
#pragma unroll
        for (int ks = 0; ks < 4; ks++) {        // 4 k-steps of 8 per chunk
            int k0 = ks * 8 + tg;
            uint32_t a[4][4], b[8][2];
#pragma unroll
            for (int mt = 0; mt < 4; mt++) {
                int r = wm * 64 + mt * 16 + g;
                a[mt][0] = __float_as_uint(As[r * SPAD + k0]);
                a[mt][1] = __float_as_uint(As[(r + 8) * SPAD + k0]);
                a[mt][2] = __float_as_uint(As[r * SPAD + k0 + 4]);
                a[mt][3] = __float_as_uint(As[(r + 8) * SPAD + k0 + 4]);
            }
#pragma unroll
            for (int j = 0; j < 8; j++) {       // n-tiles strided across gates
                int n = (j >> 1) * 64 + wn * 16 + (j & 1) * 8 + g;
                b[j][0] = __float_as_uint(Bs[n * SPAD + k0]);
                b[j][1] = __float_as_uint(Bs[n * SPAD + k0 + 4]);
            }
#pragma unroll
            for (int mt = 0; mt < 4; mt++)
#pragma unroll
                for (int j = 0; j < 8; j++)
                    mma8(acc[mt][j], a[mt], b[j]);
        }
        __syncthreads();                        // done reading cur buf before it's reloaded
    }

    // epilogue: each thread holds all 4 gates for its (row, hcol) positions
    const float* bsm = (const float*)(smem + SM_BIAS);
#pragma unroll
    for (int mt = 0; mt < 4; mt++) {
        int rbase = m0 + wm * 64 + mt * 16 + g;
#pragma unroll
        for (int sub = 0; sub < 2; sub++) {
            int hc = wn * 16 + sub * 8 + 2 * tg;     // local h-col in [0,64)
            float bi0 = bsm[hc],       bi1 = bsm[hc + 1];
            float bf0 = bsm[64 + hc],  bf1 = bsm[64 + hc + 1];
            float bg0 = bsm[128 + hc], bg1 = bsm[128 + hc + 1];
            float bo0 = bsm[192 + hc], bo1 = bsm[192 + hc + 1];
#pragma unroll
            for (int rr = 0; rr < 2; rr++) {
                int r = rbase + rr * 8;
                size_t off = (size_t)r * Hn + nbase + hc;
                float2 co = *(const float2*)(g_c + off);
                int q0 = rr * 2, q1 = rr * 2 + 1;
                float i0 = acc[mt][0 + sub][q0] + bi0, i1 = acc[mt][0 + sub][q1] + bi1;
                float f0 = acc[mt][2 + sub][q0] + bf0, f1 = acc[mt][2 + sub][q1] + bf1;
                float gg0 = acc[mt][4 + sub][q0] + bg0, gg1 = acc[mt][4 + sub][q1] + bg1;
                float o0 = acc[mt][6 + sub][q0] + bo0, o1 = acc[mt][6 + sub][q1] + bo1;
                float cn0 = sigf(f0) * co.x + sigf(i0) * tanhf_(gg0);
                float cn1 = sigf(f1) * co.y + sigf(i1) * tanhf_(gg1);
                float hn0 = tf32r(sigf(o0) * tanhf_(cn0));
                float hn1 = tf32r(sigf(o1) * tanhf_(cn1));
                *(float2*)(g_c + off) = make_float2(cn0, cn1);
                *(float2*)(g_h + off) = make_float2(hn0, hn1);
            }
        }
    }
}

// ---------------- final FC: out[b,o] = h[b,:] . w_fc[o,:] + b_fc[o] ----------------
__global__ void fc_kernel(const float* __restrict__ w_fc, const float* __restrict__ b_fc,
                          float* __restrict__ out) {
    __shared__ float hs[Hn];
    int b = blockIdx.x;
    const float4* hsrc = (const float4*)(g_h + (size_t)b * Hn);
    for (int i = threadIdx.x; i < Hn / 4; i += 64) ((float4*)hs)[i] = hsrc[i];
    __syncthreads();
    int o = threadIdx.x;
    const float4* wr = (const float4*)(w_fc + (size_t)o * Hn);
    float acc = 0.0f;
#pragma unroll 8
    for (int k = 0; k < Hn / 4; k++) {
        float4 w4 = wr[k];
        float4 h4 = ((const float4*)hs)[k];
        acc += w4.x * h4.x + w4.y * h4.y + w4.z * h4.z + w4.w * h4.w;
    }
    out[b * On + o] = acc + b_fc[o];
}

extern "C" void kernel_launch(void* const* d_in, const int* in_sizes, int n_in,
                              void* d_out, int out_size) {
    (void)in_sizes; (void)n_in; (void)out_size;
    const float* x    = (const float*)d_in[0];
    const float* w_ih = (const float*)d_in[1];
    const float* w_hh = (const float*)d_in[2];
    const float* b_ih = (const float*)d_in[3];
    const float* b_hh = (const float*)d_in[4];
    const float* w_fc = (const float*)d_in[5];
    const float* b_fc = (const float*)d_in[6];
    float* out = (float*)d_out;

    cudaFuncSetAttribute(lstm_step_kernel, cudaFuncAttributeMaxDynamicSharedMemorySize, SMEM_BYTES);

    init_hc_kernel<<<(Bn * Hn) / 256, 256>>>();
    prep_w_kernel<<<(G4 * K_TOT + 255) / 256, 256>>>(w_ih, w_hh);
    prep_x_kernel<<<(Bn * Tn * In) / 256, 256>>>(x);

    dim3 grid(Bn / MT, Hn / 64);   // 8 x 16 = 128 CTAs
    for (int t = 0; t < Tn; t++)
        lstm_step_kernel<<<grid, 256, SMEM_BYTES>>>(t, b_ih, b_hh);

    fc_kernel<<<Bn, 64>>>(w_fc, b_fc, out);
}